// round 5
// baseline (speedup 1.0000x reference)
#include <cuda_runtime.h>
#include <cuda_bf16.h>
#include <cstdint>

#define B_ 4
#define D_ 1024
#define S_ 2048

// ---------------------------------------------------------------------------
// Scratch (static __device__ arrays; allocation-free)
// ---------------------------------------------------------------------------
__device__ __nv_bfloat16 g_xTh[(size_t)B_ * S_ * D_];
__device__ __nv_bfloat16 g_xTl[(size_t)B_ * S_ * D_];
__device__ __nv_bfloat16 g_Wqh[(size_t)D_ * D_];
__device__ __nv_bfloat16 g_Wql[(size_t)D_ * D_];
__device__ __nv_bfloat16 g_Wkh[(size_t)D_ * D_];
__device__ __nv_bfloat16 g_Wkl[(size_t)D_ * D_];
__device__ __nv_bfloat16 g_Wvh[(size_t)D_ * D_];
__device__ __nv_bfloat16 g_Wvl[(size_t)D_ * D_];
__device__ __nv_bfloat16 g_Qh[(size_t)B_ * S_ * D_];
__device__ __nv_bfloat16 g_Ql[(size_t)B_ * S_ * D_];
__device__ __nv_bfloat16 g_Kh[(size_t)B_ * S_ * D_];
__device__ __nv_bfloat16 g_Kl[(size_t)B_ * S_ * D_];
__device__ __nv_bfloat16 g_Vh[(size_t)B_ * D_ * S_];
__device__ __nv_bfloat16 g_Vl[(size_t)B_ * D_ * S_];
__device__ float         g_S [(size_t)B_ * S_ * S_];
__device__ __nv_bfloat16 g_Ph[(size_t)B_ * S_ * S_];
__device__ __nv_bfloat16 g_Pl[(size_t)B_ * S_ * S_];

// ---------------------------------------------------------------------------
// PTX helpers (all sm_80-era features; compile on compute_103)
// ---------------------------------------------------------------------------
__device__ __forceinline__ uint32_t smem_to_u32(const void* p) {
    uint32_t a;
    asm("{ .reg .u64 t; cvta.to.shared.u64 t, %1; cvt.u32.u64 %0, t; }"
        : "=r"(a) : "l"(p));
    return a;
}

#define CP_ASYNC16(dst_u32, src_ptr) \
    asm volatile("cp.async.cg.shared.global [%0], [%1], 16;" \
                 :: "r"(dst_u32), "l"(src_ptr) : "memory")

#define CP_COMMIT() asm volatile("cp.async.commit_group;" ::: "memory")

#define CP_WAIT(N) asm volatile("cp.async.wait_group %0;" :: "n"(N) : "memory")

#define LDSM4(R, addr) \
    asm volatile("ldmatrix.sync.aligned.m8n8.x4.shared.b16 {%0,%1,%2,%3}, [%4];" \
                 : "=r"((R)[0]), "=r"((R)[1]), "=r"((R)[2]), "=r"((R)[3]) \
                 : "r"(addr))

#define MMA16816(D, A, Bf) \
    asm volatile("mma.sync.aligned.m16n8k16.row.col.f32.bf16.bf16.f32 " \
                 "{%0,%1,%2,%3}, {%4,%5,%6,%7}, {%8,%9}, {%0,%1,%2,%3};" \
                 : "+f"((D)[0]), "+f"((D)[1]), "+f"((D)[2]), "+f"((D)[3]) \
                 : "r"((A)[0]), "r"((A)[1]), "r"((A)[2]), "r"((A)[3]), \
                   "r"((Bf)[0]), "r"((Bf)[1]))

__device__ __forceinline__ void split1(float v, __nv_bfloat16& h, __nv_bfloat16& l) {
    h = __float2bfloat16(v);
    l = __float2bfloat16(v - __bfloat162float(h));
}

// ---------------------------------------------------------------------------
// Tensor-core GEMM via mma.sync: D[m,n] = sum_k A[m,k]*B[n,k]
// 3-term bf16 split: Ah*Bh + Ah*Bl + Al*Bh  (fp32 accumulate)
// MODE 0: bf16 hi/lo out, +bias[n]   (Q,K projection)
// MODE 1: bf16 hi/lo out, +bias[m]   (V projection)
// MODE 2: fp32 out * 1/32            (scores)
// MODE 3: fp32 out                   (attn @ V)
//
// CTA tile 128x128, BK=32, 256 threads (8 warps: 4 in M x 2 in N),
// warp tile 32x64 (2x8 m16n8k16). 3-stage cp.async circular pipeline,
// ONE __syncthreads per K-chunk.
// Smem row pitch 80B (32 bf16 + 16B pad) -> conflict-free ldmatrix.
// B stored [n][k] == col-major KxN: NON-trans ldmatrix feeds mma.row.col.
// ---------------------------------------------------------------------------
#define TILE_BYTES 10240            // 128 rows * 80B
#define STAGE_BYTES (4 * TILE_BYTES)
#define NSTAGE 3

template <int KEL, int MODE>
__global__ __launch_bounds__(256, 1) void tc_gemm(
    const __nv_bfloat16* __restrict__ Ah, const __nv_bfloat16* __restrict__ Al,
    size_t sA,
    const __nv_bfloat16* __restrict__ Bh, const __nv_bfloat16* __restrict__ Bl,
    size_t sB,
    const float* __restrict__ bias,
    float* __restrict__ outF,
    __nv_bfloat16* __restrict__ outH, __nv_bfloat16* __restrict__ outL,
    size_t sO, int ldo)
{
    extern __shared__ char smem[];
    const uint32_t smem_base = smem_to_u32(smem);
    const int tid = threadIdx.x;
    const int wid = tid >> 5;
    const int lid = tid & 31;
    const int wm = wid >> 1;          // 0..3 (M)
    const int wn = wid & 1;           // 0..1 (N)
    const int b = blockIdx.z;
    const int m0 = blockIdx.y * 128;
    const int n0 = blockIdx.x * 128;

    Ah += (size_t)b * sA; Al += (size_t)b * sA;
    Bh += (size_t)b * sB; Bl += (size_t)b * sB;

    float acc[2][8][4];
    #pragma unroll
    for (int i = 0; i < 2; ++i)
        #pragma unroll
        for (int j = 0; j < 8; ++j)
            #pragma unroll
            for (int k = 0; k < 4; ++k) acc[i][j][k] = 0.f;

    constexpr int NC = KEL / 32;

    // per-thread load coords (fixed)
    const int r_ld  = tid >> 1;                    // row 0..127
    const int c16a  = (tid & 1) * 2;               // 16B chunks {0,1} or {2,3}
    // each thread does 2 consecutive 16B chunks per tile => 4 chunks over 2 thr

    // ---- async load of one 32-wide K chunk into stage (c % 3) ----
    auto load_chunk = [&](int c) {
        const int koff = c * 32;
        const uint32_t sbase = smem_base + (uint32_t)(c % NSTAGE) * STAGE_BYTES;
        #pragma unroll
        for (int i = 0; i < 2; ++i) {
            const int c16 = c16a + i;              // 16B chunk 0..3
            const uint32_t d = sbase + (uint32_t)(r_ld * 80 + c16 * 16);
            const size_t ga = (size_t)(m0 + r_ld) * KEL + koff + c16 * 8;
            const size_t gb = (size_t)(n0 + r_ld) * KEL + koff + c16 * 8;
            CP_ASYNC16(d + 0 * TILE_BYTES, Ah + ga);
            CP_ASYNC16(d + 1 * TILE_BYTES, Al + ga);
            CP_ASYNC16(d + 2 * TILE_BYTES, Bh + gb);
            CP_ASYNC16(d + 3 * TILE_BYTES, Bl + gb);
        }
        CP_COMMIT();
    };

    load_chunk(0);
    load_chunk(1);

    const int rowA = wm * 32 + (lid & 15);
    const int rowB = wn * 64 + (lid & 15);
    const uint32_t kb = (uint32_t)((lid >> 4) * 16);  // k-subcol byte offset

    #pragma unroll 1
    for (int c = 0; c < NC; ++c) {
        if (c + 1 < NC) { CP_WAIT(1); } else { CP_WAIT(0); }
        __syncthreads();
        if (c + 2 < NC) load_chunk(c + 2);   // slot (c+2)%3 freed last iter

        const uint32_t sbase = smem_base + (uint32_t)(c % NSTAGE) * STAGE_BYTES;
        #pragma unroll
        for (int ks = 0; ks < 2; ++ks) {
            const uint32_t kbyte = (uint32_t)(ks * 32) + kb;
            uint32_t ah[2][4], alr[2][4];
            #pragma unroll
            for (int mt = 0; mt < 2; ++mt) {
                const uint32_t addr =
                    sbase + (uint32_t)((rowA + mt * 16) * 80) + kbyte;
                LDSM4(ah[mt], addr);
                LDSM4(alr[mt], addr + TILE_BYTES);
            }
            uint32_t bh[8][2], bl[8][2];
            #pragma unroll
            for (int np = 0; np < 4; ++np) {
                const uint32_t addr = sbase + 2 * TILE_BYTES +
                    (uint32_t)((rowB + np * 16) * 80) + kbyte;
                uint32_t t4[4];
                LDSM4(t4, addr);          // non-trans: B[n][k] IS col-major KxN
                bh[2 * np][0] = t4[0]; bh[2 * np][1] = t4[2];
                bh[2 * np + 1][0] = t4[1]; bh[2 * np + 1][1] = t4[3];
                LDSM4(t4, addr + TILE_BYTES);
                bl[2 * np][0] = t4[0]; bl[2 * np][1] = t4[2];
                bl[2 * np + 1][0] = t4[1]; bl[2 * np + 1][1] = t4[3];
            }
            #pragma unroll
            for (int mt = 0; mt < 2; ++mt)
                #pragma unroll
                for (int nt = 0; nt < 8; ++nt) {
                    MMA16816(acc[mt][nt], ah[mt], bh[nt]);
                    MMA16816(acc[mt][nt], ah[mt], bl[nt]);
                    MMA16816(acc[mt][nt], alr[mt], bh[nt]);
                }
        }
    }

    // ---- epilogue ----
    const int g = lid >> 2, t4i = lid & 3;
    #pragma unroll
    for (int mt = 0; mt < 2; ++mt) {
        const int m = m0 + wm * 32 + mt * 16 + g;
        float bm0 = 0.f, bm8 = 0.f;
        if (MODE == 1) { bm0 = bias[m]; bm8 = bias[m + 8]; }
        #pragma unroll
        for (int nt = 0; nt < 8; ++nt) {
            const int n = n0 + wn * 64 + nt * 8 + 2 * t4i;
            float v0 = acc[mt][nt][0], v1 = acc[mt][nt][1];
            float v2 = acc[mt][nt][2], v3 = acc[mt][nt][3];
            if (MODE == 0) {
                const float bn0 = bias[n], bn1 = bias[n + 1];
                v0 += bn0; v1 += bn1; v2 += bn0; v3 += bn1;
            } else if (MODE == 1) {
                v0 += bm0; v1 += bm0; v2 += bm8; v3 += bm8;
            } else if (MODE == 2) {
                v0 *= 0.03125f; v1 *= 0.03125f; v2 *= 0.03125f; v3 *= 0.03125f;
            }
            if (MODE == 0 || MODE == 1) {
                __nv_bfloat16 h0, l0, h1, l1;
                const size_t o0 = (size_t)b * sO + (size_t)m * ldo + n;
                split1(v0, h0, l0); split1(v1, h1, l1);
                { __nv_bfloat162 hh; hh.x = h0; hh.y = h1;
                  __nv_bfloat162 ll; ll.x = l0; ll.y = l1;
                  *(__nv_bfloat162*)(outH + o0) = hh;
                  *(__nv_bfloat162*)(outL + o0) = ll; }
                const size_t o8 = (size_t)b * sO + (size_t)(m + 8) * ldo + n;
                split1(v2, h0, l0); split1(v3, h1, l1);
                { __nv_bfloat162 hh; hh.x = h0; hh.y = h1;
                  __nv_bfloat162 ll; ll.x = l0; ll.y = l1;
                  *(__nv_bfloat162*)(outH + o8) = hh;
                  *(__nv_bfloat162*)(outL + o8) = ll; }
            } else {
                float2 f0; f0.x = v0; f0.y = v1;
                float2 f8; f8.x = v2; f8.y = v3;
                *(float2*)(outF + (size_t)b * sO + (size_t)m * ldo + n) = f0;
                *(float2*)(outF + (size_t)b * sO + (size_t)(m + 8) * ldo + n) = f8;
            }
        }
    }
}

// ---------------------------------------------------------------------------
// fp32 -> bf16 hi/lo split for all three weight matrices in one launch
// ---------------------------------------------------------------------------
__global__ __launch_bounds__(256) void wsplit3_kernel(
    const float* __restrict__ w0, const float* __restrict__ w1,
    const float* __restrict__ w2,
    __nv_bfloat16* __restrict__ h0, __nv_bfloat16* __restrict__ l0,
    __nv_bfloat16* __restrict__ h1, __nv_bfloat16* __restrict__ l1,
    __nv_bfloat16* __restrict__ h2, __nv_bfloat16* __restrict__ l2)
{
    const int which = blockIdx.y;
    const float* w = (which == 0) ? w0 : (which == 1) ? w1 : w2;
    __nv_bfloat16* h = (which == 0) ? h0 : (which == 1) ? h1 : h2;
    __nv_bfloat16* l = (which == 0) ? l0 : (which == 1) ? l1 : l2;
    const int n = D_ * D_;
    for (int i = blockIdx.x * 256 + threadIdx.x; i < n; i += gridDim.x * 256) {
        __nv_bfloat16 hi, lo;
        split1(w[i], hi, lo);
        h[i] = hi; l[i] = lo;
    }
}

// ---------------------------------------------------------------------------
// x[b,d,s] -> xT[b,s,d] with bf16 hi/lo split
// ---------------------------------------------------------------------------
__global__ __launch_bounds__(256) void xpose_split_kernel(const float* __restrict__ x)
{
    __shared__ float t[32][33];
    const int b = blockIdx.z;
    const int d0 = blockIdx.y * 32;
    const int s0 = blockIdx.x * 32;
    const int tx = threadIdx.x & 31;
    const int ty = threadIdx.x >> 5;   // 0..7
    const float* X = x + (size_t)b * D_ * S_;

    #pragma unroll
    for (int i = 0; i < 4; ++i)
        t[ty + i * 8][tx] = X[(size_t)(d0 + ty + i * 8) * S_ + s0 + tx];
    __syncthreads();
    #pragma unroll
    for (int i = 0; i < 4; ++i) {
        const int s = s0 + ty + i * 8;
        const int d = d0 + tx;
        const float v = t[tx][ty + i * 8];
        __nv_bfloat16 hi, lo;
        split1(v, hi, lo);
        const size_t idx = (size_t)b * S_ * D_ + (size_t)s * D_ + d;
        g_xTh[idx] = hi;
        g_xTl[idx] = lo;
    }
}

// ---------------------------------------------------------------------------
// softmax over rows of g_S, output bf16 hi/lo P
// ---------------------------------------------------------------------------
__global__ __launch_bounds__(256) void softmax_split_kernel()
{
    const size_t row = blockIdx.x;  // 0 .. B_*S_-1
    const float* __restrict__ p = g_S + row * S_;
    __nv_bfloat16* __restrict__ ph = g_Ph + row * S_;
    __nv_bfloat16* __restrict__ pl = g_Pl + row * S_;
    const int tid = threadIdx.x;

    float v[8];
    #pragma unroll
    for (int i = 0; i < 8; ++i) v[i] = p[i * 256 + tid];

    float m = v[0];
    #pragma unroll
    for (int i = 1; i < 8; ++i) m = fmaxf(m, v[i]);

    __shared__ float red[8];
    #pragma unroll
    for (int o = 16; o > 0; o >>= 1)
        m = fmaxf(m, __shfl_xor_sync(0xffffffffu, m, o));
    if ((tid & 31) == 0) red[tid >> 5] = m;
    __syncthreads();
    m = red[0];
    #pragma unroll
    for (int i = 1; i < 8; ++i) m = fmaxf(m, red[i]);
    __syncthreads();

    float s = 0.f;
    #pragma unroll
    for (int i = 0; i < 8; ++i) { v[i] = expf(v[i] - m); s += v[i]; }
    #pragma unroll
    for (int o = 16; o > 0; o >>= 1)
        s += __shfl_xor_sync(0xffffffffu, s, o);
    if ((tid & 31) == 0) red[tid >> 5] = s;
    __syncthreads();
    s = 0.f;
    #pragma unroll
    for (int i = 0; i < 8; ++i) s += red[i];

    const float inv = 1.0f / s;
    #pragma unroll
    for (int i = 0; i < 8; ++i) {
        __nv_bfloat16 hi, lo;
        split1(v[i] * inv, hi, lo);
        ph[i * 256 + tid] = hi;
        pl[i * 256 + tid] = lo;
    }
}

// ---------------------------------------------------------------------------
extern "C" void kernel_launch(void* const* d_in, const int* in_sizes, int n_in,
                              void* d_out, int out_size)
{
    const float* x  = (const float*)d_in[0];
    const float* Wq = (const float*)d_in[1];
    const float* bq = (const float*)d_in[2];
    const float* Wk = (const float*)d_in[3];
    const float* bk = (const float*)d_in[4];
    const float* Wv = (const float*)d_in[5];
    const float* bv = (const float*)d_in[6];
    float* out = (float*)d_out;

    const int SMEM_SZ = NSTAGE * STAGE_BYTES;   // 122880

    cudaFuncSetAttribute(tc_gemm<1024, 0>, cudaFuncAttributeMaxDynamicSharedMemorySize, SMEM_SZ);
    cudaFuncSetAttribute(tc_gemm<1024, 1>, cudaFuncAttributeMaxDynamicSharedMemorySize, SMEM_SZ);
    cudaFuncSetAttribute(tc_gemm<1024, 2>, cudaFuncAttributeMaxDynamicSharedMemorySize, SMEM_SZ);
    cudaFuncSetAttribute(tc_gemm<2048, 3>, cudaFuncAttributeMaxDynamicSharedMemorySize, SMEM_SZ);

    __nv_bfloat16 *xTh, *xTl, *Wqh, *Wql, *Wkh, *Wkl, *Wvh, *Wvl;
    __nv_bfloat16 *Qh, *Ql, *Kh, *Kl, *Vh, *Vl, *Ph, *Pl;
    float* Sc;
    cudaGetSymbolAddress((void**)&xTh, g_xTh);
    cudaGetSymbolAddress((void**)&xTl, g_xTl);
    cudaGetSymbolAddress((void**)&Wqh, g_Wqh);
    cudaGetSymbolAddress((void**)&Wql, g_Wql);
    cudaGetSymbolAddress((void**)&Wkh, g_Wkh);
    cudaGetSymbolAddress((void**)&Wkl, g_Wkl);
    cudaGetSymbolAddress((void**)&Wvh, g_Wvh);
    cudaGetSymbolAddress((void**)&Wvl, g_Wvl);
    cudaGetSymbolAddress((void**)&Qh, g_Qh);
    cudaGetSymbolAddress((void**)&Ql, g_Ql);
    cudaGetSymbolAddress((void**)&Kh, g_Kh);
    cudaGetSymbolAddress((void**)&Kl, g_Kl);
    cudaGetSymbolAddress((void**)&Vh, g_Vh);
    cudaGetSymbolAddress((void**)&Vl, g_Vl);
    cudaGetSymbolAddress((void**)&Ph, g_Ph);
    cudaGetSymbolAddress((void**)&Pl, g_Pl);
    cudaGetSymbolAddress((void**)&Sc, g_S);

    const size_t SD = (size_t)S_ * D_;
    const size_t SS = (size_t)S_ * S_;

    // 1) operand preparation
    wsplit3_kernel<<<dim3(64, 3), 256>>>(Wq, Wk, Wv, Wqh, Wql, Wkh, Wkl, Wvh, Wvl);
    xpose_split_kernel<<<dim3(S_ / 32, D_ / 32, B_), 256>>>(x);

    // 2) projections
    // Q[s,e] = xT[s,:].W_q[e,:] + bq[e]
    tc_gemm<1024, 0><<<dim3(D_ / 128, S_ / 128, B_), 256, SMEM_SZ>>>(
        xTh, xTl, SD, Wqh, Wql, 0, bq, nullptr, Qh, Ql, SD, D_);
    tc_gemm<1024, 0><<<dim3(D_ / 128, S_ / 128, B_), 256, SMEM_SZ>>>(
        xTh, xTl, SD, Wkh, Wkl, 0, bk, nullptr, Kh, Kl, SD, D_);
    // V[e,t] = W_v[e,:].xT[t,:] + bv[e]   (swapped operands -> [e,t] layout)
    tc_gemm<1024, 1><<<dim3(S_ / 128, D_ / 128, B_), 256, SMEM_SZ>>>(
        Wvh, Wvl, 0, xTh, xTl, SD, bv, nullptr, Vh, Vl, SD, S_);

    // 3) scores S[s,t] = Q[s,:].K[t,:] / 32
    tc_gemm<1024, 2><<<dim3(S_ / 128, S_ / 128, B_), 256, SMEM_SZ>>>(
        Qh, Ql, SD, Kh, Kl, SD, nullptr, Sc, nullptr, nullptr, SS, S_);

    // 4) softmax rows -> P hi/lo
    softmax_split_kernel<<<B_ * S_, 256>>>();

    // 5) out[s,e] = P[s,:].V[e,:]
    tc_gemm<2048, 3><<<dim3(D_ / 128, S_ / 128, B_), 256, SMEM_SZ>>>(
        Ph, Pl, SS, Vh, Vl, SD, nullptr, out, nullptr, nullptr, SD, D_);
}

// round 6
// speedup vs baseline: 1.1054x; 1.1054x over previous
#include <cuda_runtime.h>
#include <cuda_bf16.h>
#include <cstdint>

#define B_ 4
#define D_ 1024
#define S_ 2048

// ---------------------------------------------------------------------------
// Scratch (static __device__ arrays; allocation-free)
// ---------------------------------------------------------------------------
__device__ __nv_bfloat16 g_xTh[(size_t)B_ * S_ * D_];
__device__ __nv_bfloat16 g_xTl[(size_t)B_ * S_ * D_];
__device__ __nv_bfloat16 g_Wqh[(size_t)D_ * D_];
__device__ __nv_bfloat16 g_Wql[(size_t)D_ * D_];
__device__ __nv_bfloat16 g_Wkh[(size_t)D_ * D_];
__device__ __nv_bfloat16 g_Wkl[(size_t)D_ * D_];
__device__ __nv_bfloat16 g_Wvh[(size_t)D_ * D_];
__device__ __nv_bfloat16 g_Wvl[(size_t)D_ * D_];
__device__ __nv_bfloat16 g_Qh[(size_t)B_ * S_ * D_];
__device__ __nv_bfloat16 g_Ql[(size_t)B_ * S_ * D_];
__device__ __nv_bfloat16 g_Kh[(size_t)B_ * S_ * D_];
__device__ __nv_bfloat16 g_Kl[(size_t)B_ * S_ * D_];
__device__ __nv_bfloat16 g_Vh[(size_t)B_ * D_ * S_];
__device__ __nv_bfloat16 g_Vl[(size_t)B_ * D_ * S_];
__device__ float         g_S [(size_t)B_ * S_ * S_];
__device__ __nv_bfloat16 g_Ph[(size_t)B_ * S_ * S_];
__device__ __nv_bfloat16 g_Pl[(size_t)B_ * S_ * S_];

// ---------------------------------------------------------------------------
// PTX helpers (all sm_80-era features; compile on compute_103)
// ---------------------------------------------------------------------------
__device__ __forceinline__ uint32_t smem_to_u32(const void* p) {
    uint32_t a;
    asm("{ .reg .u64 t; cvta.to.shared.u64 t, %1; cvt.u32.u64 %0, t; }"
        : "=r"(a) : "l"(p));
    return a;
}

#define CP_ASYNC16(dst_u32, src_ptr) \
    asm volatile("cp.async.cg.shared.global [%0], [%1], 16;" \
                 :: "r"(dst_u32), "l"(src_ptr) : "memory")

#define CP_COMMIT() asm volatile("cp.async.commit_group;" ::: "memory")

#define CP_WAIT(N) asm volatile("cp.async.wait_group %0;" :: "n"(N) : "memory")

#define LDSM4(R, addr) \
    asm volatile("ldmatrix.sync.aligned.m8n8.x4.shared.b16 {%0,%1,%2,%3}, [%4];" \
                 : "=r"((R)[0]), "=r"((R)[1]), "=r"((R)[2]), "=r"((R)[3]) \
                 : "r"(addr))

#define MMA16816(D, A, Bf) \
    asm volatile("mma.sync.aligned.m16n8k16.row.col.f32.bf16.bf16.f32 " \
                 "{%0,%1,%2,%3}, {%4,%5,%6,%7}, {%8,%9}, {%0,%1,%2,%3};" \
                 : "+f"((D)[0]), "+f"((D)[1]), "+f"((D)[2]), "+f"((D)[3]) \
                 : "r"((A)[0]), "r"((A)[1]), "r"((A)[2]), "r"((A)[3]), \
                   "r"((Bf)[0]), "r"((Bf)[1]))

__device__ __forceinline__ void split1(float v, __nv_bfloat16& h, __nv_bfloat16& l) {
    h = __float2bfloat16(v);
    l = __float2bfloat16(v - __bfloat162float(h));
}

// ---------------------------------------------------------------------------
// Tensor-core GEMM via mma.sync: D[m,n] = sum_k A[m,k]*B[n,k]
// 3-term bf16 split: Ah*Bh + Ah*Bl + Al*Bh  (fp32 accumulate)
// MODE 0: bf16 hi/lo out, +bias[n]   (Q,K projection)
// MODE 1: bf16 hi/lo out, +bias[m]   (V projection)
// MODE 2: fp32 out * 1/32            (scores)
// MODE 3: fp32 out                   (attn @ V)
//
// CTA tile 128x64, BK=32, 256 threads (8 warps: 4 in M x 2 in N),
// warp tile 32x32 (2x4 m16n8k16). 2-stage double buffer (round-4 structure).
// Smem 60KB + regs<=128 -> 2 CTAs/SM (16 warps) for latency hiding.
// Smem row pitch 80B -> conflict-free ldmatrix.
// B stored [n][k] == col-major KxN: NON-trans ldmatrix feeds mma.row.col.
// ---------------------------------------------------------------------------
#define TILE_A_BYTES 10240          // 128 rows * 80B
#define TILE_B_BYTES 5120           // 64 rows * 80B
#define STAGE_BYTES (2 * TILE_A_BYTES + 2 * TILE_B_BYTES)   // 30720
#define OFF_AL TILE_A_BYTES
#define OFF_BH (2 * TILE_A_BYTES)
#define OFF_BL (2 * TILE_A_BYTES + TILE_B_BYTES)

template <int KEL, int MODE>
__global__ __launch_bounds__(256, 2) void tc_gemm(
    const __nv_bfloat16* __restrict__ Ah, const __nv_bfloat16* __restrict__ Al,
    size_t sA,
    const __nv_bfloat16* __restrict__ Bh, const __nv_bfloat16* __restrict__ Bl,
    size_t sB,
    const float* __restrict__ bias,
    float* __restrict__ outF,
    __nv_bfloat16* __restrict__ outH, __nv_bfloat16* __restrict__ outL,
    size_t sO, int ldo)
{
    extern __shared__ char smem[];
    const uint32_t smem_base = smem_to_u32(smem);
    const int tid = threadIdx.x;
    const int wid = tid >> 5;
    const int lid = tid & 31;
    const int wm = wid >> 1;          // 0..3 (M)
    const int wn = wid & 1;           // 0..1 (N)
    const int b = blockIdx.z;
    const int m0 = blockIdx.y * 128;
    const int n0 = blockIdx.x * 64;

    Ah += (size_t)b * sA; Al += (size_t)b * sA;
    Bh += (size_t)b * sB; Bl += (size_t)b * sB;

    float acc[2][4][4];
    #pragma unroll
    for (int i = 0; i < 2; ++i)
        #pragma unroll
        for (int j = 0; j < 4; ++j)
            #pragma unroll
            for (int k = 0; k < 4; ++k) acc[i][j][k] = 0.f;

    constexpr int NC = KEL / 32;

    // per-thread load coords
    const int rA_ld  = tid >> 1;                // 0..127
    const int cA_ld  = (tid & 1) * 2;           // 16B chunks {0,1} or {2,3}
    const int rB_ld  = tid >> 2;                // 0..63
    const int cB_ld  = tid & 3;                 // 16B chunk 0..3

    // ---- async load of one 32-wide K chunk into stage (c & 1) ----
    auto load_chunk = [&](int c) {
        const int koff = c * 32;
        const uint32_t sbase = smem_base + (uint32_t)(c & 1) * STAGE_BYTES;
        #pragma unroll
        for (int i = 0; i < 2; ++i) {
            const int c16 = cA_ld + i;
            const uint32_t d = sbase + (uint32_t)(rA_ld * 80 + c16 * 16);
            const size_t ga = (size_t)(m0 + rA_ld) * KEL + koff + c16 * 8;
            CP_ASYNC16(d, Ah + ga);
            CP_ASYNC16(d + OFF_AL, Al + ga);
        }
        {
            const uint32_t d = sbase + (uint32_t)(rB_ld * 80 + cB_ld * 16);
            const size_t gb = (size_t)(n0 + rB_ld) * KEL + koff + cB_ld * 8;
            CP_ASYNC16(d + OFF_BH, Bh + gb);
            CP_ASYNC16(d + OFF_BL, Bl + gb);
        }
        CP_COMMIT();
    };

    load_chunk(0);

    const int rowA = wm * 32 + (lid & 15);
    const int rowB = wn * 32 + (lid & 15);
    const uint32_t kb = (uint32_t)((lid >> 4) * 16);  // k-subcol byte offset

    #pragma unroll 1
    for (int c = 0; c < NC; ++c) {
        if (c + 1 < NC) load_chunk(c + 1);
        if (c + 1 < NC) { CP_WAIT(1); } else { CP_WAIT(0); }
        __syncthreads();

        const uint32_t sbase = smem_base + (uint32_t)(c & 1) * STAGE_BYTES;
        #pragma unroll
        for (int ks = 0; ks < 2; ++ks) {
            const uint32_t kbyte = (uint32_t)(ks * 32) + kb;
            uint32_t ah[2][4], alr[2][4];
            #pragma unroll
            for (int mt = 0; mt < 2; ++mt) {
                const uint32_t addr =
                    sbase + (uint32_t)((rowA + mt * 16) * 80) + kbyte;
                LDSM4(ah[mt], addr);
                LDSM4(alr[mt], addr + OFF_AL);
            }
            uint32_t bh[4][2], bl[4][2];
            #pragma unroll
            for (int np = 0; np < 2; ++np) {
                const uint32_t addr = sbase + OFF_BH +
                    (uint32_t)((rowB + np * 16) * 80) + kbyte;
                uint32_t t4[4];
                LDSM4(t4, addr);          // non-trans: B[n][k] IS col-major KxN
                bh[2 * np][0] = t4[0]; bh[2 * np][1] = t4[2];
                bh[2 * np + 1][0] = t4[1]; bh[2 * np + 1][1] = t4[3];
                LDSM4(t4, addr + TILE_B_BYTES);
                bl[2 * np][0] = t4[0]; bl[2 * np][1] = t4[2];
                bl[2 * np + 1][0] = t4[1]; bl[2 * np + 1][1] = t4[3];
            }
            #pragma unroll
            for (int mt = 0; mt < 2; ++mt)
                #pragma unroll
                for (int nt = 0; nt < 4; ++nt) {
                    MMA16816(acc[mt][nt], ah[mt], bh[nt]);
                    MMA16816(acc[mt][nt], ah[mt], bl[nt]);
                    MMA16816(acc[mt][nt], alr[mt], bh[nt]);
                }
        }
        __syncthreads();   // protect stage before next-next load overwrites
    }

    // ---- epilogue ----
    const int g = lid >> 2, t4i = lid & 3;
    #pragma unroll
    for (int mt = 0; mt < 2; ++mt) {
        const int m = m0 + wm * 32 + mt * 16 + g;
        float bm0 = 0.f, bm8 = 0.f;
        if (MODE == 1) { bm0 = bias[m]; bm8 = bias[m + 8]; }
        #pragma unroll
        for (int nt = 0; nt < 4; ++nt) {
            const int n = n0 + wn * 32 + nt * 8 + 2 * t4i;
            float v0 = acc[mt][nt][0], v1 = acc[mt][nt][1];
            float v2 = acc[mt][nt][2], v3 = acc[mt][nt][3];
            if (MODE == 0) {
                const float bn0 = bias[n], bn1 = bias[n + 1];
                v0 += bn0; v1 += bn1; v2 += bn0; v3 += bn1;
            } else if (MODE == 1) {
                v0 += bm0; v1 += bm0; v2 += bm8; v3 += bm8;
            } else if (MODE == 2) {
                v0 *= 0.03125f; v1 *= 0.03125f; v2 *= 0.03125f; v3 *= 0.03125f;
            }
            if (MODE == 0 || MODE == 1) {
                __nv_bfloat16 h0, l0, h1, l1;
                const size_t o0 = (size_t)b * sO + (size_t)m * ldo + n;
                split1(v0, h0, l0); split1(v1, h1, l1);
                { __nv_bfloat162 hh; hh.x = h0; hh.y = h1;
                  __nv_bfloat162 ll; ll.x = l0; ll.y = l1;
                  *(__nv_bfloat162*)(outH + o0) = hh;
                  *(__nv_bfloat162*)(outL + o0) = ll; }
                const size_t o8 = (size_t)b * sO + (size_t)(m + 8) * ldo + n;
                split1(v2, h0, l0); split1(v3, h1, l1);
                { __nv_bfloat162 hh; hh.x = h0; hh.y = h1;
                  __nv_bfloat162 ll; ll.x = l0; ll.y = l1;
                  *(__nv_bfloat162*)(outH + o8) = hh;
                  *(__nv_bfloat162*)(outL + o8) = ll; }
            } else {
                float2 f0; f0.x = v0; f0.y = v1;
                float2 f8; f8.x = v2; f8.y = v3;
                *(float2*)(outF + (size_t)b * sO + (size_t)m * ldo + n) = f0;
                *(float2*)(outF + (size_t)b * sO + (size_t)(m + 8) * ldo + n) = f8;
            }
        }
    }
}

// ---------------------------------------------------------------------------
// fp32 -> bf16 hi/lo split for all three weight matrices in one launch
// ---------------------------------------------------------------------------
__global__ __launch_bounds__(256) void wsplit3_kernel(
    const float* __restrict__ w0, const float* __restrict__ w1,
    const float* __restrict__ w2,
    __nv_bfloat16* __restrict__ h0, __nv_bfloat16* __restrict__ l0,
    __nv_bfloat16* __restrict__ h1, __nv_bfloat16* __restrict__ l1,
    __nv_bfloat16* __restrict__ h2, __nv_bfloat16* __restrict__ l2)
{
    const int which = blockIdx.y;
    const float* w = (which == 0) ? w0 : (which == 1) ? w1 : w2;
    __nv_bfloat16* h = (which == 0) ? h0 : (which == 1) ? h1 : h2;
    __nv_bfloat16* l = (which == 0) ? l0 : (which == 1) ? l1 : l2;
    const int n = D_ * D_;
    for (int i = blockIdx.x * 256 + threadIdx.x; i < n; i += gridDim.x * 256) {
        __nv_bfloat16 hi, lo;
        split1(w[i], hi, lo);
        h[i] = hi; l[i] = lo;
    }
}

// ---------------------------------------------------------------------------
// x[b,d,s] -> xT[b,s,d] with bf16 hi/lo split
// ---------------------------------------------------------------------------
__global__ __launch_bounds__(256) void xpose_split_kernel(const float* __restrict__ x)
{
    __shared__ float t[32][33];
    const int b = blockIdx.z;
    const int d0 = blockIdx.y * 32;
    const int s0 = blockIdx.x * 32;
    const int tx = threadIdx.x & 31;
    const int ty = threadIdx.x >> 5;   // 0..7
    const float* X = x + (size_t)b * D_ * S_;

    #pragma unroll
    for (int i = 0; i < 4; ++i)
        t[ty + i * 8][tx] = X[(size_t)(d0 + ty + i * 8) * S_ + s0 + tx];
    __syncthreads();
    #pragma unroll
    for (int i = 0; i < 4; ++i) {
        const int s = s0 + ty + i * 8;
        const int d = d0 + tx;
        const float v = t[tx][ty + i * 8];
        __nv_bfloat16 hi, lo;
        split1(v, hi, lo);
        const size_t idx = (size_t)b * S_ * D_ + (size_t)s * D_ + d;
        g_xTh[idx] = hi;
        g_xTl[idx] = lo;
    }
}

// ---------------------------------------------------------------------------
// softmax over rows of g_S, output bf16 hi/lo P
// ---------------------------------------------------------------------------
__global__ __launch_bounds__(256) void softmax_split_kernel()
{
    const size_t row = blockIdx.x;  // 0 .. B_*S_-1
    const float* __restrict__ p = g_S + row * S_;
    __nv_bfloat16* __restrict__ ph = g_Ph + row * S_;
    __nv_bfloat16* __restrict__ pl = g_Pl + row * S_;
    const int tid = threadIdx.x;

    float v[8];
    #pragma unroll
    for (int i = 0; i < 8; ++i) v[i] = p[i * 256 + tid];

    float m = v[0];
    #pragma unroll
    for (int i = 1; i < 8; ++i) m = fmaxf(m, v[i]);

    __shared__ float red[8];
    #pragma unroll
    for (int o = 16; o > 0; o >>= 1)
        m = fmaxf(m, __shfl_xor_sync(0xffffffffu, m, o));
    if ((tid & 31) == 0) red[tid >> 5] = m;
    __syncthreads();
    m = red[0];
    #pragma unroll
    for (int i = 1; i < 8; ++i) m = fmaxf(m, red[i]);
    __syncthreads();

    float s = 0.f;
    #pragma unroll
    for (int i = 0; i < 8; ++i) { v[i] = expf(v[i] - m); s += v[i]; }
    #pragma unroll
    for (int o = 16; o > 0; o >>= 1)
        s += __shfl_xor_sync(0xffffffffu, s, o);
    if ((tid & 31) == 0) red[tid >> 5] = s;
    __syncthreads();
    s = 0.f;
    #pragma unroll
    for (int i = 0; i < 8; ++i) s += red[i];

    const float inv = 1.0f / s;
    #pragma unroll
    for (int i = 0; i < 8; ++i) {
        __nv_bfloat16 hi, lo;
        split1(v[i] * inv, hi, lo);
        ph[i * 256 + tid] = hi;
        pl[i * 256 + tid] = lo;
    }
}

// ---------------------------------------------------------------------------
extern "C" void kernel_launch(void* const* d_in, const int* in_sizes, int n_in,
                              void* d_out, int out_size)
{
    const float* x  = (const float*)d_in[0];
    const float* Wq = (const float*)d_in[1];
    const float* bq = (const float*)d_in[2];
    const float* Wk = (const float*)d_in[3];
    const float* bk = (const float*)d_in[4];
    const float* Wv = (const float*)d_in[5];
    const float* bv = (const float*)d_in[6];
    float* out = (float*)d_out;

    const int SMEM_SZ = 2 * STAGE_BYTES;   // 61440

    cudaFuncSetAttribute(tc_gemm<1024, 0>, cudaFuncAttributeMaxDynamicSharedMemorySize, SMEM_SZ);
    cudaFuncSetAttribute(tc_gemm<1024, 1>, cudaFuncAttributeMaxDynamicSharedMemorySize, SMEM_SZ);
    cudaFuncSetAttribute(tc_gemm<1024, 2>, cudaFuncAttributeMaxDynamicSharedMemorySize, SMEM_SZ);
    cudaFuncSetAttribute(tc_gemm<2048, 3>, cudaFuncAttributeMaxDynamicSharedMemorySize, SMEM_SZ);

    __nv_bfloat16 *xTh, *xTl, *Wqh, *Wql, *Wkh, *Wkl, *Wvh, *Wvl;
    __nv_bfloat16 *Qh, *Ql, *Kh, *Kl, *Vh, *Vl, *Ph, *Pl;
    float* Sc;
    cudaGetSymbolAddress((void**)&xTh, g_xTh);
    cudaGetSymbolAddress((void**)&xTl, g_xTl);
    cudaGetSymbolAddress((void**)&Wqh, g_Wqh);
    cudaGetSymbolAddress((void**)&Wql, g_Wql);
    cudaGetSymbolAddress((void**)&Wkh, g_Wkh);
    cudaGetSymbolAddress((void**)&Wkl, g_Wkl);
    cudaGetSymbolAddress((void**)&Wvh, g_Wvh);
    cudaGetSymbolAddress((void**)&Wvl, g_Wvl);
    cudaGetSymbolAddress((void**)&Qh, g_Qh);
    cudaGetSymbolAddress((void**)&Ql, g_Ql);
    cudaGetSymbolAddress((void**)&Kh, g_Kh);
    cudaGetSymbolAddress((void**)&Kl, g_Kl);
    cudaGetSymbolAddress((void**)&Vh, g_Vh);
    cudaGetSymbolAddress((void**)&Vl, g_Vl);
    cudaGetSymbolAddress((void**)&Ph, g_Ph);
    cudaGetSymbolAddress((void**)&Pl, g_Pl);
    cudaGetSymbolAddress((void**)&Sc, g_S);

    const size_t SD = (size_t)S_ * D_;
    const size_t SS = (size_t)S_ * S_;

    // 1) operand preparation
    wsplit3_kernel<<<dim3(64, 3), 256>>>(Wq, Wk, Wv, Wqh, Wql, Wkh, Wkl, Wvh, Wvl);
    xpose_split_kernel<<<dim3(S_ / 32, D_ / 32, B_), 256>>>(x);

    // 2) projections
    // Q[s,e] = xT[s,:].W_q[e,:] + bq[e]
    tc_gemm<1024, 0><<<dim3(D_ / 64, S_ / 128, B_), 256, SMEM_SZ>>>(
        xTh, xTl, SD, Wqh, Wql, 0, bq, nullptr, Qh, Ql, SD, D_);
    tc_gemm<1024, 0><<<dim3(D_ / 64, S_ / 128, B_), 256, SMEM_SZ>>>(
        xTh, xTl, SD, Wkh, Wkl, 0, bk, nullptr, Kh, Kl, SD, D_);
    // V[e,t] = W_v[e,:].xT[t,:] + bv[e]   (swapped operands -> [e,t] layout)
    tc_gemm<1024, 1><<<dim3(S_ / 64, D_ / 128, B_), 256, SMEM_SZ>>>(
        Wvh, Wvl, 0, xTh, xTl, SD, bv, nullptr, Vh, Vl, SD, S_);

    // 3) scores S[s,t] = Q[s,:].K[t,:] / 32
    tc_gemm<1024, 2><<<dim3(S_ / 64, S_ / 128, B_), 256, SMEM_SZ>>>(
        Qh, Ql, SD, Kh, Kl, SD, nullptr, Sc, nullptr, nullptr, SS, S_);

    // 4) softmax rows -> P hi/lo
    softmax_split_kernel<<<B_ * S_, 256>>>();

    // 5) out[s,e] = P[s,:].V[e,:]
    tc_gemm<2048, 3><<<dim3(D_ / 64, S_ / 128, B_), 256, SMEM_SZ>>>(
        Ph, Pl, SS, Vh, Vl, SD, nullptr, out, nullptr, nullptr, SD, D_);
}